// round 15
// baseline (speedup 1.0000x reference)
#include <cuda_runtime.h>
#include <cuda_bf16.h>
#include <cstdint>

// PLIF neuron scan, T=8. x: [B=32,T=8,S=131072] fp32 -> spikes same shape.
//
// R15: isolate WRITE-burst shape. Loads/scan = champion (8 front-batched
// LDG.128, MLP=8). Stores: spikes staged in smem, then emitted as 8x 4KB
// cp.async.bulk (shared->global) contiguous bursts per CTA, replacing
// fine-grained interleaved 16B STGs. Tests whether DRAM write scheduling
// granularity contributes to the ~5.7 TB/s mixed-stream plateau.

#define VTH 0.5f
#define S4C 32768u      // spatial float4 per (b,t) = 128*32*32/4
#define S4_SHIFT 15
#define S4_MASK 32767

__global__ __launch_bounds__(256) void plif_kernel(
    const float4* __restrict__ x,
    const float* __restrict__ w,
    float4* __restrict__ out)
{
    __shared__ float4 sbuf[8][256];   // 32KB: spikes for 8 timesteps

    unsigned tid = threadIdx.x;
    unsigned i = blockIdx.x * 256u + tid;           // 0..1048575 exact
    unsigned b = i >> S4_SHIFT;
    unsigned s = i & S4_MASK;

    float wv = __ldg(w);
    float tau = 1.0f / (1.0f + __expf(-wv));

    unsigned base = (b << 3) * S4C + s;             // (b, t=0, s)
    const float4* px = x + base;

    // Front-batch all 8 timestep loads (independent of the scan) -> MLP=8.
    float4 xv[8];
#pragma unroll
    for (int t = 0; t < 8; t++) {
        xv[t] = __ldcs(px + t * S4C);
    }

    // Sequential membrane scan; stage each spike vector in smem.
    float4 m = make_float4(0.f, 0.f, 0.f, 0.f);
#pragma unroll
    for (int t = 0; t < 8; t++) {
        float4 r;

        m.x = fmaf(tau, m.x, xv[t].x);
        r.x = (m.x > VTH) ? 1.0f : 0.0f;
        m.x = (m.x > VTH) ? 0.0f : m.x;

        m.y = fmaf(tau, m.y, xv[t].y);
        r.y = (m.y > VTH) ? 1.0f : 0.0f;
        m.y = (m.y > VTH) ? 0.0f : m.y;

        m.z = fmaf(tau, m.z, xv[t].z);
        r.z = (m.z > VTH) ? 1.0f : 0.0f;
        m.z = (m.z > VTH) ? 0.0f : m.z;

        m.w = fmaf(tau, m.w, xv[t].w);
        r.w = (m.w > VTH) ? 1.0f : 0.0f;
        m.w = (m.w > VTH) ? 0.0f : m.w;

        sbuf[t][tid] = r;
    }

    __syncthreads();
    asm volatile("fence.proxy.async.shared::cta;" ::: "memory");

    // One thread emits 8 contiguous 4KB bulk writes (one per t-plane chunk).
    if (tid == 0) {
        unsigned site0 = blockIdx.x * 256u;              // CTA's first site
        unsigned b0 = site0 >> S4_SHIFT;
        unsigned s0 = site0 & S4_MASK;
        float4* po = out + (b0 << 3) * S4C + s0;

        uint32_t saddr;
        asm("{ .reg .u64 t; cvta.to.shared.u64 t, %1; cvt.u32.u64 %0, t; }"
            : "=r"(saddr) : "l"(&sbuf[0][0]));

#pragma unroll
        for (int t = 0; t < 8; t++) {
            asm volatile(
                "cp.async.bulk.global.shared::cta.bulk_group [%0], [%1], %2;"
                :: "l"(po + t * S4C), "r"(saddr + t * 4096u), "n"(4096)
                : "memory");
        }
        asm volatile("cp.async.bulk.commit_group;" ::: "memory");
        // Must drain before CTA exit (smem lifetime).
        asm volatile("cp.async.bulk.wait_group 0;" ::: "memory");
    }
}

extern "C" void kernel_launch(void* const* d_in, const int* in_sizes, int n_in,
                              void* d_out, int out_size) {
    const float4* x = (const float4*)d_in[0];
    const float* w = (const float*)d_in[1];
    float4* o = (float4*)d_out;

    // 1,048,576 float4 sites -> exact 4096 x 256 grid
    plif_kernel<<<4096, 256>>>(x, w, o);
}

// round 16
// speedup vs baseline: 1.0894x; 1.0894x over previous
#include <cuda_runtime.h>
#include <cuda_bf16.h>

// PLIF neuron scan, T=8. x: [B=32,T=8,C=128,H=32,W=32] fp32 -> spikes, same
// shape. FINAL KERNEL (champion configuration, verified rounds 3 & 14).
//
// Roofline analysis: 268 MB irreducible streaming traffic (128MB read +
// 128MB write, zero reuse); binding constraint is the sustained mixed
// read/write DRAM rate, measured at a ~5.7-5.9 TB/s plateau invariant under:
//   MLP 4/8/16, occupancy 26-84%, read policy (cs/lu/evict_first), write
//   policy (cs/wt/evict_last), L2 residency hints (full/partial sticky),
//   access width (128/256-bit), stream shape (t-inner/t-outer), wave
//   structure (oversubscribed/single-wave), and write path (STG/TMA bulk).
// This kernel sits at that plateau: ~37 us kernel, ~45 us wall.
//
// Structure: one thread = one float4 site (4 contiguous floats x 8
// timesteps). The 8 timestep loads are independent of the membrane
// recurrence -> front-batched for MLP=8; the sequential scan runs in
// registers; each spike vector is stored immediately (52 regs, no spill,
// 4 CTAs/SM). 4096 CTAs oversubscribe ~7 waves deep, which self-balances
// across SMs (single-wave variant regressed 14%).

#define VTH 0.5f
#define S4C 32768u      // spatial float4 per (b,t) = 128*32*32/4
#define S4_SHIFT 15
#define S4_MASK 32767

__global__ __launch_bounds__(256) void plif_kernel(
    const float4* __restrict__ x,
    const float* __restrict__ w,
    float4* __restrict__ out)
{
    unsigned i = blockIdx.x * 256u + threadIdx.x;   // 0..1048575 exact
    unsigned b = i >> S4_SHIFT;
    unsigned s = i & S4_MASK;

    float wv = __ldg(w);
    float tau = 1.0f / (1.0f + __expf(-wv));

    unsigned base = (b << 3) * S4C + s;             // (b, t=0, s)
    const float4* px = x + base;
    float4* po = out + base;

    // Front-batch all 8 timestep loads (independent of the scan) -> MLP=8.
    float4 xv[8];
#pragma unroll
    for (int t = 0; t < 8; t++) {
        xv[t] = __ldcs(px + t * S4C);
    }

    // Sequential membrane scan; store each spike vector immediately.
    float4 m = make_float4(0.f, 0.f, 0.f, 0.f);
#pragma unroll
    for (int t = 0; t < 8; t++) {
        float4 r;

        m.x = fmaf(tau, m.x, xv[t].x);
        r.x = (m.x > VTH) ? 1.0f : 0.0f;
        m.x = (m.x > VTH) ? 0.0f : m.x;

        m.y = fmaf(tau, m.y, xv[t].y);
        r.y = (m.y > VTH) ? 1.0f : 0.0f;
        m.y = (m.y > VTH) ? 0.0f : m.y;

        m.z = fmaf(tau, m.z, xv[t].z);
        r.z = (m.z > VTH) ? 1.0f : 0.0f;
        m.z = (m.z > VTH) ? 0.0f : m.z;

        m.w = fmaf(tau, m.w, xv[t].w);
        r.w = (m.w > VTH) ? 1.0f : 0.0f;
        m.w = (m.w > VTH) ? 0.0f : m.w;

        __stcs(po + t * S4C, r);
    }
}

extern "C" void kernel_launch(void* const* d_in, const int* in_sizes, int n_in,
                              void* d_out, int out_size) {
    const float4* x = (const float4*)d_in[0];
    const float* w = (const float*)d_in[1];
    float4* o = (float4*)d_out;

    // 1,048,576 float4 sites -> exact 4096 x 256 grid
    plif_kernel<<<4096, 256>>>(x, w, o);
}

// round 17
// speedup vs baseline: 1.0902x; 1.0007x over previous
#include <cuda_runtime.h>
#include <cuda_bf16.h>

// PLIF neuron scan, T=8. x: [B=32,T=8,C=128,H=32,W=32] fp32 -> spikes, same
// shape. FINAL KERNEL (champion configuration; reproduced rounds 3, 14, 16:
// wall 45.06 / 45.22 / 45.09 us, kernel 36.8-37.5 us, rel_err 0.0).
//
// Roofline: 268 MB irreducible streaming traffic (128MB read + 128MB write,
// zero reuse). Binding constraint = sustained mixed read/write DRAM rate,
// measured plateau ~5.7-5.9 TB/s, invariant under (all tested, R1-R15):
//   MLP 4/8/16 | occupancy 26-84% | read policy cs/lu/evict_first |
//   write policy cs/wt/evict_last | L2 residency full/partial sticky |
//   access width 128/256-bit | stream shape t-inner/t-outer |
//   wave structure oversubscribed/single-wave | store path STG/TMA bulk.
// End-to-end: 268MB / 45.1us = 5.9 TB/s (~74% of 8 TB/s paper spec).
//
// Structure: one thread = one float4 site (4 contiguous floats x 8
// timesteps). The 8 timestep loads are independent of the membrane
// recurrence -> front-batched for MLP=8; the sequential scan runs in
// registers; each spike vector stores immediately (52 regs, no spill,
// 4 CTAs/SM). 4096 CTAs oversubscribe ~7 waves deep, which self-balances
// across SMs (single-wave persistent variant regressed 14%).

#define VTH 0.5f
#define S4C 32768u      // spatial float4 per (b,t) = 128*32*32/4
#define S4_SHIFT 15
#define S4_MASK 32767

__global__ __launch_bounds__(256) void plif_kernel(
    const float4* __restrict__ x,
    const float* __restrict__ w,
    float4* __restrict__ out)
{
    unsigned i = blockIdx.x * 256u + threadIdx.x;   // 0..1048575 exact
    unsigned b = i >> S4_SHIFT;
    unsigned s = i & S4_MASK;

    float wv = __ldg(w);
    float tau = 1.0f / (1.0f + __expf(-wv));

    unsigned base = (b << 3) * S4C + s;             // (b, t=0, s)
    const float4* px = x + base;
    float4* po = out + base;

    // Front-batch all 8 timestep loads (independent of the scan) -> MLP=8.
    float4 xv[8];
#pragma unroll
    for (int t = 0; t < 8; t++) {
        xv[t] = __ldcs(px + t * S4C);
    }

    // Sequential membrane scan; store each spike vector immediately.
    float4 m = make_float4(0.f, 0.f, 0.f, 0.f);
#pragma unroll
    for (int t = 0; t < 8; t++) {
        float4 r;

        m.x = fmaf(tau, m.x, xv[t].x);
        r.x = (m.x > VTH) ? 1.0f : 0.0f;
        m.x = (m.x > VTH) ? 0.0f : m.x;

        m.y = fmaf(tau, m.y, xv[t].y);
        r.y = (m.y > VTH) ? 1.0f : 0.0f;
        m.y = (m.y > VTH) ? 0.0f : m.y;

        m.z = fmaf(tau, m.z, xv[t].z);
        r.z = (m.z > VTH) ? 1.0f : 0.0f;
        m.z = (m.z > VTH) ? 0.0f : m.z;

        m.w = fmaf(tau, m.w, xv[t].w);
        r.w = (m.w > VTH) ? 1.0f : 0.0f;
        m.w = (m.w > VTH) ? 0.0f : m.w;

        __stcs(po + t * S4C, r);
    }
}

extern "C" void kernel_launch(void* const* d_in, const int* in_sizes, int n_in,
                              void* d_out, int out_size) {
    const float4* x = (const float4*)d_in[0];
    const float* w = (const float*)d_in[1];
    float4* o = (float4*)d_out;

    // 1,048,576 float4 sites -> exact 4096 x 256 grid
    plif_kernel<<<4096, 256>>>(x, w, o);
}